// round 16
// baseline (speedup 1.0000x reference)
#include <cuda_runtime.h>
#include <cuda_fp16.h>

#define N_NODES 50000
#define N_EDGES 800000
#define IN_F    128
#define NHF     128      // N_HEADS * OUT_FEATS
#define SLOPE   0.2f
#define NB_SCAN ((N_NODES + 1023) / 1024)   // 49

// fp16 tiles: As[128][136] + Ws[128][136] halves
#define GEMM_SMEM_BYTES (2 * 128 * 136 * 2)   // 69632

// ---------------- scratch (static __device__, no allocation) ----------------
__device__ __align__(16) __half g_fs[N_NODES * NHF];    // feat_src projection (fp16)
__device__ __align__(16) __half g_fd[N_NODES * NHF];    // feat_dst projection (fp16)
__device__ int g_deg[N_NODES];
__device__ int g_off[N_NODES + 1];
__device__ int g_rank[N_EDGES];   // edge's arrival rank within its dst bucket
__device__ int g_esrc[N_EDGES];   // CSR payload: src node id per edge (by dst)
__device__ int g_bsum[NB_SCAN];

// ---------------- helpers ----------------
__device__ __forceinline__ void mma_f16(
    float& c0, float& c1, float& c2, float& c3,
    unsigned a0, unsigned a1, unsigned a2, unsigned a3,
    unsigned b0, unsigned b1)
{
    asm volatile(
        "mma.sync.aligned.m16n8k16.row.col.f32.f16.f16.f32 "
        "{%0,%1,%2,%3}, {%4,%5,%6,%7}, {%8,%9}, {%0,%1,%2,%3};\n"
        : "+f"(c0), "+f"(c1), "+f"(c2), "+f"(c3)
        : "r"(a0), "r"(a1), "r"(a2), "r"(a3), "r"(b0), "r"(b1));
}

__device__ __forceinline__ void ldsm_x4(
    unsigned& r0, unsigned& r1, unsigned& r2, unsigned& r3, unsigned saddr)
{
    asm volatile(
        "ldmatrix.sync.aligned.m8n8.x4.shared.b16 {%0,%1,%2,%3}, [%4];"
        : "=r"(r0), "=r"(r1), "=r"(r2), "=r"(r3) : "r"(saddr));
}

__device__ __forceinline__ float4 h4_to_f4(uint2 u) {
    const __half2 h0 = *reinterpret_cast<const __half2*>(&u.x);
    const __half2 h1 = *reinterpret_cast<const __half2*>(&u.y);
    const float2 a = __half22float2(h0);
    const float2 b = __half22float2(h1);
    return make_float4(a.x, a.y, b.x, b.y);
}

// ---------------- fp16 tensor-core projection GEMM (ldmatrix) ----------------
// C[m, n] = sum_k feat[m,k] * W[n,k] + b[n]
// 128x128 tile/block, 8 warps (4m x 2n), m16n8k16 over 8 K-steps.
// Fragments via ldmatrix.x4 (6 per warp per K-step vs 24 scalar LDS).
// 2 CTAs/SM (launch_bounds minBlocks=2) so staging overlaps compute.
__global__ __launch_bounds__(256, 2) void proj_gemm(
    const float* __restrict__ feat,
    const float* __restrict__ Wsrc, const float* __restrict__ bsrc,
    const float* __restrict__ Wdst, const float* __restrict__ bdst,
    const float* __restrict__ Wres, const float* __restrict__ bres,
    float* __restrict__ out_res)
{
    const int mat = blockIdx.y;
    const float* W = (mat == 0) ? Wsrc : (mat == 1) ? Wdst : Wres;
    const float* b = (mat == 0) ? bsrc : (mat == 1) ? bdst : bres;
    __half* outh   = (mat == 0) ? g_fs : g_fd;

    const int m0 = blockIdx.x * 128;

    extern __shared__ __align__(16) __half smh[];
    __half* As = smh;                  // [128][136]
    __half* Ws = smh + 128 * 136;      // [128][136]

    const int tid = threadIdx.x;
    const int wid = tid >> 5;
    const int lane = tid & 31;
    const int warp_m = wid >> 1;
    const int warp_n = wid & 1;
    const int g  = lane >> 2;
    const int tg = lane & 3;

    // ---- stage both operands, fp32 -> fp16 (rn) ----
#pragma unroll 4
    for (int it = 0; it < 16; it++) {
        const int i = tid + it * 256;
        const int row = i >> 5;
        const int c4  = i & 31;
        int gm = m0 + row;
        if (gm >= N_NODES) gm = N_NODES - 1;
        const float4 va = *reinterpret_cast<const float4*>(&feat[gm * IN_F + c4 * 4]);
        __half2* ap = reinterpret_cast<__half2*>(&As[row * 136 + c4 * 4]);
        ap[0] = __floats2half2_rn(va.x, va.y);
        ap[1] = __floats2half2_rn(va.z, va.w);

        const float4 vb = *reinterpret_cast<const float4*>(&W[row * IN_F + c4 * 4]);
        __half2* bp = reinterpret_cast<__half2*>(&Ws[row * 136 + c4 * 4]);
        bp[0] = __floats2half2_rn(vb.x, vb.y);
        bp[1] = __floats2half2_rn(vb.z, vb.w);
    }
    __syncthreads();

    // ---- ldmatrix lane addresses (bytes into shared space) ----
    const unsigned smem_u32 = (unsigned)__cvta_generic_to_shared(smh);
    // A, per m16 tile t: lanes 0-15 -> rows mb+(l&15), k-lo; lanes 16-31 same rows, k-hi
    unsigned aAddr[2];
#pragma unroll
    for (int t = 0; t < 2; t++) {
        const int mb = warp_m * 32 + t * 16;
        const int row = mb + (lane & 15);
        const int k8  = (lane >> 4) * 8;
        aAddr[t] = smem_u32 + (unsigned)(row * 136 + k8) * 2u;
    }
    // B, per n16 pair jj: tiles {n-lo/k-lo, n-lo/k-hi, n-hi/k-lo, n-hi/k-hi}
    unsigned bAddr[4];
#pragma unroll
    for (int jj = 0; jj < 4; jj++) {
        const int nb = warp_n * 64 + jj * 16;
        const int row = nb + ((lane >> 4) << 3) + (lane & 7);
        const int k8  = ((lane >> 3) & 1) * 8;
        bAddr[jj] = smem_u32 + (unsigned)(128 * 136 + row * 136 + k8) * 2u;
    }

    float acc[2][8][4];
#pragma unroll
    for (int t = 0; t < 2; t++)
#pragma unroll
        for (int j = 0; j < 8; j++)
#pragma unroll
            for (int c = 0; c < 4; c++) acc[t][j][c] = 0.0f;

#pragma unroll
    for (int ks = 0; ks < 8; ks++) {
        const unsigned koff = ks * 32u;          // 16 halves = 32 bytes
        unsigned af[2][4];
        ldsm_x4(af[0][0], af[0][1], af[0][2], af[0][3], aAddr[0] + koff);
        ldsm_x4(af[1][0], af[1][1], af[1][2], af[1][3], aAddr[1] + koff);
#pragma unroll
        for (int jj = 0; jj < 4; jj++) {
            unsigned b0, b1, b2, b3;             // (n-lo,k-lo)(n-lo,k-hi)(n-hi,k-lo)(n-hi,k-hi)
            ldsm_x4(b0, b1, b2, b3, bAddr[jj] + koff);
            const int j0 = jj * 2, j1 = jj * 2 + 1;
            mma_f16(acc[0][j0][0], acc[0][j0][1], acc[0][j0][2], acc[0][j0][3],
                    af[0][0], af[0][1], af[0][2], af[0][3], b0, b1);
            mma_f16(acc[0][j1][0], acc[0][j1][1], acc[0][j1][2], acc[0][j1][3],
                    af[0][0], af[0][1], af[0][2], af[0][3], b2, b3);
            mma_f16(acc[1][j0][0], acc[1][j0][1], acc[1][j0][2], acc[1][j0][3],
                    af[1][0], af[1][1], af[1][2], af[1][3], b0, b1);
            mma_f16(acc[1][j1][0], acc[1][j1][1], acc[1][j1][2], acc[1][j1][3],
                    af[1][0], af[1][1], af[1][2], af[1][3], b2, b3);
        }
    }

    // ---- epilogue: bias + store ----
#pragma unroll
    for (int j = 0; j < 8; j++) {
        const int n = warp_n * 64 + j * 8 + 2 * tg;
        const float bn0 = __ldg(&b[n]);
        const float bn1 = __ldg(&b[n + 1]);
#pragma unroll
        for (int t = 0; t < 2; t++) {
            const int m = m0 + warp_m * 32 + t * 16 + g;
            const int m2 = m + 8;
            if (mat < 2) {
                if (m < N_NODES)
                    *reinterpret_cast<__half2*>(&outh[m * NHF + n]) =
                        __floats2half2_rn(acc[t][j][0] + bn0, acc[t][j][1] + bn1);
                if (m2 < N_NODES)
                    *reinterpret_cast<__half2*>(&outh[m2 * NHF + n]) =
                        __floats2half2_rn(acc[t][j][2] + bn0, acc[t][j][3] + bn1);
            } else {
                if (m < N_NODES)
                    *reinterpret_cast<float2*>(&out_res[m * NHF + n]) =
                        make_float2(acc[t][j][0] + bn0, acc[t][j][1] + bn1);
                if (m2 < N_NODES)
                    *reinterpret_cast<float2*>(&out_res[m2 * NHF + n]) =
                        make_float2(acc[t][j][2] + bn0, acc[t][j][3] + bn1);
            }
        }
    }
}

// ---------------- CSR build ----------------
// count also records each edge's rank within its dst bucket -> atomic-free fill
__global__ void count_kernel(const int* __restrict__ dst) {
    int e = blockIdx.x * blockDim.x + threadIdx.x;
    if (e < N_EDGES) g_rank[e] = atomicAdd(&g_deg[dst[e]], 1);
}

__global__ __launch_bounds__(1024) void scan_local() {
    __shared__ int warp_sums[32];
    const int i = blockIdx.x * 1024 + threadIdx.x;
    const int lane = threadIdx.x & 31;
    const int w = threadIdx.x >> 5;
    const int v = (i < N_NODES) ? g_deg[i] : 0;
    int x = v;
#pragma unroll
    for (int o = 1; o < 32; o <<= 1) {
        int y = __shfl_up_sync(0xFFFFFFFFu, x, o);
        if (lane >= o) x += y;
    }
    if (lane == 31) warp_sums[w] = x;
    __syncthreads();
    if (w == 0) {
        int ws = warp_sums[lane];
#pragma unroll
        for (int o = 1; o < 32; o <<= 1) {
            int y = __shfl_up_sync(0xFFFFFFFFu, ws, o);
            if (lane >= o) ws += y;
        }
        warp_sums[lane] = ws;
    }
    __syncthreads();
    const int pre = (w > 0) ? warp_sums[w - 1] : 0;
    if (i < N_NODES) g_off[i] = pre + x - v;
    if (threadIdx.x == 0) g_bsum[blockIdx.x] = warp_sums[31];
}

// add carries (computed in-block from g_bsum); zero g_deg for next replay
__global__ __launch_bounds__(1024) void scan_add() {
    __shared__ int s_partial[2];
    __shared__ int s_carry;
    const int tid = threadIdx.x;
    const int lane = tid & 31;
    const int w = tid >> 5;

    if (tid < 64) {
        int v = (tid < blockIdx.x) ? g_bsum[tid] : 0;   // NB_SCAN <= 64
#pragma unroll
        for (int o = 16; o > 0; o >>= 1)
            v += __shfl_xor_sync(0xFFFFFFFFu, v, o);
        if (lane == 0) s_partial[w] = v;
    }
    __syncthreads();
    if (tid == 0) s_carry = s_partial[0] + s_partial[1];
    __syncthreads();

    const int i = blockIdx.x * 1024 + tid;
    if (i < N_NODES) {
        g_off[i] += s_carry;
        g_deg[i] = 0;
    }
    if (i == 0) g_off[N_NODES] = N_EDGES;
}

// atomic-free scatter: position = off[dst] + rank (rank from count pass)
__global__ void fill_kernel(const int* __restrict__ src, const int* __restrict__ dst) {
    int e = blockIdx.x * blockDim.x + threadIdx.x;
    if (e < N_EDGES)
        g_esrc[g_off[dst[e]] + g_rank[e]] = src[e];
}

// ---------------- fused score + softmax + aggregation ----------------
// One warp per dst node; lane l owns features 4l..4l+3 (8B fp16 gather).
__global__ __launch_bounds__(256) void fused_agg(
    const float* __restrict__ attn, float* __restrict__ out)
{
    const int n = (blockIdx.x * blockDim.x + threadIdx.x) >> 5;
    const int lane = threadIdx.x & 31;
    if (n >= N_NODES) return;
    const int beg = g_off[n];
    const int end = g_off[n + 1];
    if (beg == end) return;

    const float4 fd4 = h4_to_f4(*reinterpret_cast<const uint2*>(&g_fd[n * NHF + lane * 4]));
    const float4 at4 = *reinterpret_cast<const float4*>(&attn[lane * 4]);

    float d = 0.0f;
    float4 a = make_float4(0.f, 0.f, 0.f, 0.f);

    auto score = [&](const float4& f) -> float {
        float x0 = f.x + fd4.x; x0 = (x0 > 0.f) ? x0 : SLOPE * x0;
        float x1 = f.y + fd4.y; x1 = (x1 > 0.f) ? x1 : SLOPE * x1;
        float x2 = f.z + fd4.z; x2 = (x2 > 0.f) ? x2 : SLOPE * x2;
        float x3 = f.w + fd4.w; x3 = (x3 > 0.f) ? x3 : SLOPE * x3;
        float p = x0 * at4.x;
        p = fmaf(x1, at4.y, p);
        p = fmaf(x2, at4.z, p);
        p = fmaf(x3, at4.w, p);
        p += __shfl_xor_sync(0xFFFFFFFFu, p, 1);
        p += __shfl_xor_sync(0xFFFFFFFFu, p, 2);
        p += __shfl_xor_sync(0xFFFFFFFFu, p, 4);
        return p;
    };

    auto accum = [&](const float4& f, float wt) {
        d += wt;
        a.x = fmaf(wt, f.x, a.x);
        a.y = fmaf(wt, f.y, a.y);
        a.z = fmaf(wt, f.z, a.z);
        a.w = fmaf(wt, f.w, a.w);
    };

    for (int base = beg; base < end; base += 32) {
        const int cnt = min(32, end - base);
        int s_l = (base + lane < end) ? g_esrc[base + lane] : 0;

        int k = 0;
        for (; k + 4 <= cnt; k += 4) {
            const int s0 = __shfl_sync(0xFFFFFFFFu, s_l, k);
            const int s1 = __shfl_sync(0xFFFFFFFFu, s_l, k + 1);
            const int s2 = __shfl_sync(0xFFFFFFFFu, s_l, k + 2);
            const int s3 = __shfl_sync(0xFFFFFFFFu, s_l, k + 3);
            const uint2 u0 = *reinterpret_cast<const uint2*>(&g_fs[s0 * NHF + lane * 4]);
            const uint2 u1 = *reinterpret_cast<const uint2*>(&g_fs[s1 * NHF + lane * 4]);
            const uint2 u2 = *reinterpret_cast<const uint2*>(&g_fs[s2 * NHF + lane * 4]);
            const uint2 u3 = *reinterpret_cast<const uint2*>(&g_fs[s3 * NHF + lane * 4]);
            const float4 f0 = h4_to_f4(u0);
            const float4 f1 = h4_to_f4(u1);
            const float4 f2 = h4_to_f4(u2);
            const float4 f3 = h4_to_f4(u3);
            const float p0 = score(f0);
            const float p1 = score(f1);
            const float p2 = score(f2);
            const float p3 = score(f3);
            const float w0 = __expf(p0), w1 = __expf(p1);
            const float w2 = __expf(p2), w3 = __expf(p3);
            accum(f0, w0); accum(f1, w1); accum(f2, w2); accum(f3, w3);
        }
        for (; k < cnt; k++) {
            const int s = __shfl_sync(0xFFFFFFFFu, s_l, k);
            const float4 f = h4_to_f4(*reinterpret_cast<const uint2*>(&g_fs[s * NHF + lane * 4]));
            const float p = score(f);
            accum(f, __expf(p));
        }
    }

    const float inv = 1.0f / d;
    float4* op = reinterpret_cast<float4*>(&out[n * NHF + lane * 4]);
    float4 o = *op;
    o.x += a.x * inv;
    o.y += a.y * inv;
    o.z += a.z * inv;
    o.w += a.w * inv;
    *op = o;
}

// ---------------- launcher ----------------
// Forked-capture DAG:  [fork] --GEMM(fp16 ldmatrix)--[join]--fused_agg
//                         \--count-scanL-scanA-fill--/
extern "C" void kernel_launch(void* const* d_in, const int* in_sizes, int n_in,
                              void* d_out, int out_size)
{
    const float* feat = (const float*)d_in[0];
    const float* Wsrc = (const float*)d_in[1];
    const float* bsrc = (const float*)d_in[2];
    const float* Wdst = (const float*)d_in[3];
    const float* bdst = (const float*)d_in[4];
    const float* attn = (const float*)d_in[5];
    const float* Wres = (const float*)d_in[6];
    const float* bres = (const float*)d_in[7];
    const int*   src  = (const int*)d_in[8];
    const int*   dst  = (const int*)d_in[9];
    float* out = (float*)d_out;

    cudaFuncSetAttribute(proj_gemm,
                         cudaFuncAttributeMaxDynamicSharedMemorySize,
                         GEMM_SMEM_BYTES);

    cudaStream_t s2;
    cudaEvent_t eFork, eJoin;
    cudaStreamCreateWithFlags(&s2, cudaStreamNonBlocking);
    cudaEventCreateWithFlags(&eFork, cudaEventDisableTiming);
    cudaEventCreateWithFlags(&eJoin, cudaEventDisableTiming);

    // fork: CSR chain on s2, independent of the GEMM
    cudaEventRecord(eFork, 0);
    cudaStreamWaitEvent(s2, eFork, 0);
    count_kernel<<<(N_EDGES + 255) / 256, 256, 0, s2>>>(dst);
    scan_local<<<NB_SCAN, 1024, 0, s2>>>();
    scan_add<<<NB_SCAN, 1024, 0, s2>>>();
    fill_kernel<<<(N_EDGES + 255) / 256, 256, 0, s2>>>(src, dst);
    cudaEventRecord(eJoin, s2);

    // main branch: projections (res written straight into d_out)
    dim3 ggrid((N_NODES + 127) / 128, 3);
    proj_gemm<<<ggrid, 256, GEMM_SMEM_BYTES>>>(feat, Wsrc, bsrc, Wdst, bdst, Wres, bres, out);

    // join, then fused edge phase (needs g_fs/g_fd AND the CSR)
    cudaStreamWaitEvent(0, eJoin, 0);
    fused_agg<<<(N_NODES * 32 + 255) / 256, 256>>>(attn, out);
}